// round 14
// baseline (speedup 1.0000x reference)
#include <cuda_runtime.h>
#include <cstdint>

#define D_MODEL   1024
#define NUM_HEADS 16
#define HEAD_DIM  64
#define B_SZ      4
#define T_SZ      2048
#define M_ROWS    (B_SZ * T_SZ)   // 8192

// Scratch (allocation-free rule: __device__ globals). All tf32 bit patterns.
// Arrays feeding a GEMM contraction are stored k-PAIR-PERMUTED within each
// 8-group: pos(k) = (k&~7) | ((k&3)<<1) | ((k>>2)&1).  Both operands of every
// mma use the same permutation, so results are bit-identical to natural order.
__device__ uint32_t g_xq [(size_t)M_ROWS * D_MODEL];     // permuted k
__device__ uint32_t g_xkv[(size_t)M_ROWS * D_MODEL];     // permuted k
__device__ uint32_t g_wq [(size_t)D_MODEL * D_MODEL];    // permuted k
__device__ uint32_t g_wk [(size_t)D_MODEL * D_MODEL];    // permuted k
__device__ uint32_t g_wv [(size_t)D_MODEL * D_MODEL];    // permuted k
__device__ uint32_t g_wo [(size_t)D_MODEL * D_MODEL];    // permuted k
__device__ uint32_t g_q  [(size_t)B_SZ * NUM_HEADS * T_SZ * HEAD_DIM];  // natural d, pre-scaled by 0.125*log2e
__device__ uint32_t g_k  [(size_t)B_SZ * NUM_HEADS * T_SZ * HEAD_DIM];  // PERMUTED d
__device__ uint32_t g_v  [(size_t)B_SZ * NUM_HEADS * T_SZ * HEAD_DIM];  // natural d
__device__ uint32_t g_attn[(size_t)M_ROWS * D_MODEL];                   // permuted c

// ---------------------------------------------------------------------------
// helpers
// ---------------------------------------------------------------------------
__device__ __forceinline__ uint32_t f2tf32(float x) {
    uint32_t r;
    asm("cvt.rna.tf32.f32 %0, %1;" : "=r"(r) : "f"(x));
    return r;
}
__device__ __forceinline__ float ex2(float x) {
    float r;
    asm("ex2.approx.ftz.f32 %0, %1;" : "=f"(r) : "f"(x));
    return r;
}
__device__ __forceinline__ int kperm(int c) {   // position of logical index c
    return (c & ~7) | ((c & 3) << 1) | ((c >> 2) & 1);
}

// D = A(16x8, row, tf32) * B(8x8, col, tf32) + C   (fp32 accum)
__device__ __forceinline__ void mma8(float4& d, const uint32_t* a,
                                     uint32_t b0, uint32_t b1, const float4& c) {
    asm volatile(
        "mma.sync.aligned.m16n8k8.row.col.f32.tf32.tf32.f32 "
        "{%0,%1,%2,%3}, {%4,%5,%6,%7}, {%8,%9}, {%10,%11,%12,%13};\n"
        : "=f"(d.x), "=f"(d.y), "=f"(d.z), "=f"(d.w)
        : "r"(a[0]), "r"(a[1]), "r"(a[2]), "r"(a[3]),
          "r"(b0), "r"(b1),
          "f"(c.x), "f"(c.y), "f"(c.z), "f"(c.w));
}

__device__ __forceinline__ void cpa16(uint32_t s, const void* g) {
    asm volatile("cp.async.cg.shared.global [%0], [%1], 16;" :: "r"(s), "l"(g));
}
#define CP_COMMIT() asm volatile("cp.async.commit_group;")
#define CP_WAIT(n)  asm volatile("cp.async.wait_group %0;" :: "n"(n))

// ---------------------------------------------------------------------------
// Fused fp32 -> tf32 + k-pair permutation for ALL 6 arrays in ONE launch.
// Segments: [0,1]=x arrays (4096 blocks each), [2..5]=W arrays (512 each).
// out[8i..] = {k0,k4,k1,k5,k2,k6,k3,k7}
// ---------------------------------------------------------------------------
struct CvtArgs {
    const float* src[6];
    uint32_t*    dst[6];
};

__global__ __launch_bounds__(256)
void cvtp_all_kernel(CvtArgs args)
{
    int bid = blockIdx.x;
    int seg, off;
    if (bid < 8192) { seg = bid >> 12;        off = bid & 4095; }
    else            { seg = 2 + ((bid - 8192) >> 9); off = (bid - 8192) & 511; }
    const float* src = args.src[seg];
    uint32_t*    dst = args.dst[seg];
    size_t i = (size_t)off * 256 + threadIdx.x;      // exact multiples; no bounds check
    const float* s = src + i * 8;
    float4 v0 = *(const float4*)s;
    float4 v1 = *(const float4*)(s + 4);
    uint4 o0, o1;
    o0.x = f2tf32(v0.x); o0.y = f2tf32(v1.x);
    o0.z = f2tf32(v0.y); o0.w = f2tf32(v1.y);
    o1.x = f2tf32(v0.z); o1.y = f2tf32(v1.z);
    o1.z = f2tf32(v0.w); o1.w = f2tf32(v1.w);
    *(uint4*)(dst + i * 8)     = o0;
    *(uint4*)(dst + i * 8 + 4) = o1;
}

// ---------------------------------------------------------------------------
// GEMM mainloop: BM=BN=128, BK=32, 256 threads = 8 warps (2x4 of 64x32).
// Operands pre-permuted tf32 bits: each mma fragment is ONE LDS.64 (B) or
// TWO LDS.64 (A). Smem row stride 40 words (8g+2t4 bank pattern, conflict-free).
// Double-buffered cp.async, prefetch distance 1, ONE sync per ktile:
//   wait(0); sync; stage(kti+1 -> other buf); compute(buf kti&1)
// (other buf's last reads were in iter kti-1, which completed before the sync).
// ---------------------------------------------------------------------------
#define GS 40
#define GEMM_MAIN(A_, W_)                                                      \
    extern __shared__ uint32_t smu[];                                          \
    const int tid  = threadIdx.x;                                              \
    const int lane = tid & 31;                                                 \
    const int w    = tid >> 5;                                                 \
    const int g    = lane >> 2;                                                \
    const int t4   = lane & 3;                                                 \
    const int wm   = (w >> 2) * 64;                                            \
    const int wn   = (w & 3) * 32;                                             \
    const int m0   = blockIdx.y << 7;                                          \
    const int n0   = blockIdx.x << 7;                                          \
    const uint32_t* Ap = (A_) + (size_t)m0 * D_MODEL;                          \
    const uint32_t* Wp = (W_) + (size_t)n0 * D_MODEL;                          \
    const uint32_t smb = (uint32_t)__cvta_generic_to_shared(smu);              \
    float4 acc[4][4];                                                          \
    for (int i = 0; i < 4; i++)                                                \
        for (int j = 0; j < 4; j++) acc[i][j] = make_float4(0.f,0.f,0.f,0.f);  \
    auto stage = [&](int kt, int buf) {                                        \
        uint32_t sA = smb + (uint32_t)(buf * 10240) * 4;                       \
        uint32_t sB = sA + 5120u * 4;                                          \
        _Pragma("unroll")                                                      \
        for (int i = 0; i < 4; i++) {                                          \
            int c  = tid + (i << 8);          /* 0..1023 */                    \
            int r  = c >> 3;                                                   \
            int c8 = (c & 7) << 2;                                             \
            cpa16(sA + (uint32_t)(r * GS + c8) * 4,                            \
                  Ap + (size_t)r * D_MODEL + kt + c8);                         \
            cpa16(sB + (uint32_t)(r * GS + c8) * 4,                            \
                  Wp + (size_t)r * D_MODEL + kt + c8);                         \
        }                                                                      \
    };                                                                         \
    stage(0, 0);  CP_COMMIT();                                                 \
    for (int kti = 0; kti < 32; kti++) {                                       \
        CP_WAIT(0);                                                            \
        __syncthreads();                                                       \
        if (kti + 1 < 32) { stage((kti + 1) << 5, (kti + 1) & 1); CP_COMMIT(); } \
        const uint32_t* As = smu + (kti & 1) * 10240;                          \
        const uint32_t* Bs = As + 5120;                                        \
        _Pragma("unroll")                                                      \
        for (int ks = 0; ks < 4; ks++) {                                       \
            const int kk2 = ks * 8 + t4 * 2;                                   \
            uint32_t a[4][4], bb[4][2];                                        \
            _Pragma("unroll")                                                  \
            for (int mt = 0; mt < 4; mt++) {                                   \
                int m = wm + mt * 16 + g;                                      \
                uint2 u = *(const uint2*)&As[m * GS + kk2];                    \
                uint2 v = *(const uint2*)&As[(m + 8) * GS + kk2];              \
                a[mt][0] = u.x; a[mt][1] = v.x;                                \
                a[mt][2] = u.y; a[mt][3] = v.y;                                \
            }                                                                  \
            _Pragma("unroll")                                                  \
            for (int nt = 0; nt < 4; nt++) {                                   \
                int n = wn + nt * 8 + g;                                       \
                uint2 p = *(const uint2*)&Bs[n * GS + kk2];                    \
                bb[nt][0] = p.x; bb[nt][1] = p.y;                              \
            }                                                                  \
            _Pragma("unroll")                                                  \
            for (int mt = 0; mt < 4; mt++)                                     \
                _Pragma("unroll")                                              \
                for (int nt = 0; nt < 4; nt++)                                 \
                    mma8(acc[mt][nt], a[mt], bb[nt][0], bb[nt][1], acc[mt][nt]);\
        }                                                                      \
    }

// ---------------------------------------------------------------------------
// Fused Q/K/V projection. Epilogue scatters to (b,h,t,d) tf32 bits.
// Q: pre-scaled by 0.125*log2e, natural d. K: d-PERMUTED. V: natural d.
// ---------------------------------------------------------------------------
__global__ __launch_bounds__(256, 2)
void gemm_qkv_kernel()
{
    const uint32_t* Asel; const uint32_t* Wsel; uint32_t* Csel; float scale = 1.0f;
    if (blockIdx.z == 0)      { Asel = g_xq;  Wsel = g_wq; Csel = g_q; scale = 0.18033688011112042f; }
    else if (blockIdx.z == 1) { Asel = g_xkv; Wsel = g_wk; Csel = g_k; }
    else                      { Asel = g_xkv; Wsel = g_wv; Csel = g_v; }
    const bool permK = (blockIdx.z == 1);

    GEMM_MAIN(Asel, Wsel)

#pragma unroll
    for (int mt = 0; mt < 4; mt++) {
        int r1 = m0 + wm + mt * 16 + g;
        int r2 = r1 + 8;
        int b1 = r1 >> 11, t1 = r1 & 2047;
        int b2 = r2 >> 11, t2 = r2 & 2047;
#pragma unroll
        for (int nt = 0; nt < 4; nt++) {
            int c0 = n0 + wn + nt * 8 + 2 * t4;
            int hh = c0 >> 6, d0 = c0 & 63;
            uint32_t q00 = f2tf32(acc[mt][nt].x * scale);
            uint32_t q01 = f2tf32(acc[mt][nt].y * scale);
            uint32_t q10 = f2tf32(acc[mt][nt].z * scale);
            uint32_t q11 = f2tf32(acc[mt][nt].w * scale);
            size_t base1 = (((size_t)b1 * NUM_HEADS + hh) * T_SZ + t1) * HEAD_DIM;
            size_t base2 = (((size_t)b2 * NUM_HEADS + hh) * T_SZ + t2) * HEAD_DIM;
            if (permK) {
                int p0 = kperm(d0), p1 = kperm(d0 + 1);
                Csel[base1 + p0] = q00;  Csel[base1 + p1] = q01;
                Csel[base2 + p0] = q10;  Csel[base2 + p1] = q11;
            } else {
                *(uint2*)&Csel[base1 + d0] = make_uint2(q00, q01);
                *(uint2*)&Csel[base2 + d0] = make_uint2(q10, q11);
            }
        }
    }
}

// ---------------------------------------------------------------------------
// Output projection: A = g_attn (permuted c), W = g_wo (permuted k),
// C = fp32 row-major (natural N).
// ---------------------------------------------------------------------------
__global__ __launch_bounds__(256, 2)
void gemm_o_kernel(float* __restrict__ C)
{
    GEMM_MAIN(g_attn, g_wo)

#pragma unroll
    for (int mt = 0; mt < 4; mt++) {
        int r1 = m0 + wm + mt * 16 + g;
        int r2 = r1 + 8;
#pragma unroll
        for (int nt = 0; nt < 4; nt++) {
            int c0 = n0 + wn + nt * 8 + 2 * t4;
            *(float2*)&C[(size_t)r1 * D_MODEL + c0] =
                make_float2(acc[mt][nt].x, acc[mt][nt].y);
            *(float2*)&C[(size_t)r2 * D_MODEL + c0] =
                make_float2(acc[mt][nt].z, acc[mt][nt].w);
        }
    }
}

// ---------------------------------------------------------------------------
// Causal flash attention, tf32 mma.sync, base-2 online softmax.
// K is d-permuted in gmem -> S-loop B fragment = ONE LDS.64 (stride 72,
// conflict-free). V natural, stride 72. P round-trips smem (stride 72).
// Single sync per k-tile (prefetch-after-sync, distance 1).
// Smem (words): K0@0 K1@4608 V0@9216 V1@13824 P@18432(128x72); 110592 B.
// ---------------------------------------------------------------------------
__global__ __launch_bounds__(128, 2)
void attn_tc_kernel(const uint32_t* __restrict__ Qg, const uint32_t* __restrict__ Kg,
                    const uint32_t* __restrict__ Vg, uint32_t* __restrict__ Og)
{
    extern __shared__ uint32_t smu[];
    const int KS0 = 0, KS1 = 4608, VS0 = 9216, VS1 = 13824, PSO = 18432;
    uint32_t* Psm = smu + PSO;

    const int tid  = threadIdx.x;
    const int lane = tid & 31;
    const int wm   = tid >> 5;
    const int g    = lane >> 2;
    const int t4   = lane & 3;
    const int qt   = (int)(gridDim.x - 1) - (int)blockIdx.x;  // long blocks first
    const int q0   = qt << 7;
    const int h    = blockIdx.y;
    const int b    = blockIdx.z;

    const size_t base = ((size_t)(b * NUM_HEADS + h)) * T_SZ * HEAD_DIM;
    const uint32_t smb = (uint32_t)__cvta_generic_to_shared(smu);
    const float NEG_INF = __int_as_float(0xff800000);

    // ---- stage Q (natural, pre-scaled) into KS0 rows 0-63 / VS0 rows 64-127 ----
    {
        const uint32_t* Qp = Qg + base + (size_t)q0 * HEAD_DIM;
#pragma unroll
        for (int i = 0; i < 16; i++) {
            int c  = tid + (i << 7);
            int r  = c >> 4;
            int c4 = (c & 15) << 2;
            int off = (r < 64) ? (KS0 + r * 72 + c4) : (VS0 + (r - 64) * 72 + c4);
            cpa16(smb + (uint32_t)off * 4, Qp + r * 64 + c4);
        }
    }
    CP_COMMIT(); CP_WAIT(0);
    __syncthreads();

    // ---- Q fragments -> registers ----
    uint32_t qa[2][8][4];
#pragma unroll
    for (int mt = 0; mt < 2; mt++) {
        const uint32_t* Qs = smu + (mt ? VS0 : KS0);
        const int row = wm * 16 + g;
#pragma unroll
        for (int ks = 0; ks < 8; ks++) {
            int kk = ks * 8 + t4;
            qa[mt][ks][0] = Qs[row * 72 + kk];
            qa[mt][ks][1] = Qs[(row + 8) * 72 + kk];
            qa[mt][ks][2] = Qs[row * 72 + kk + 4];
            qa[mt][ks][3] = Qs[(row + 8) * 72 + kk + 4];
        }
    }
    __syncthreads();

    auto stageKV = [&](int kt, int buf) {
        const uint32_t* Kp = Kg + base + (size_t)(kt << 6) * HEAD_DIM;
        const uint32_t* Vp = Vg + base + (size_t)(kt << 6) * HEAD_DIM;
        const int ko = buf ? KS1 : KS0;
        const int vo = buf ? VS1 : VS0;
#pragma unroll
        for (int i = 0; i < 8; i++) {
            int c  = tid + (i << 7);
            int r  = c >> 4;
            int c4 = (c & 15) << 2;
            cpa16(smb + (uint32_t)(ko + r * 72 + c4) * 4, Kp + r * 64 + c4);
            cpa16(smb + (uint32_t)(vo + r * 72 + c4) * 4, Vp + r * 64 + c4);
        }
    };

    stageKV(0, 0); CP_COMMIT();

    float4 o[2][8];
#pragma unroll
    for (int mt = 0; mt < 2; mt++)
#pragma unroll
        for (int dt = 0; dt < 8; dt++) o[mt][dt] = make_float4(0.f, 0.f, 0.f, 0.f);
    float mrow[2][2] = {{NEG_INF, NEG_INF}, {NEG_INF, NEG_INF}};
    float lrow[2][2] = {{0.f, 0.f}, {0.f, 0.f}};

    const int nkt = 2 * qt + 2;
    for (int kt = 0; kt < nkt; kt++) {
        CP_WAIT(0);
        __syncthreads();   // K/V(kt) ready; all reads of the other buffer done
        if (kt + 1 < nkt) { stageKV(kt + 1, (kt + 1) & 1); CP_COMMIT(); }

        const uint32_t* Kt = smu + ((kt & 1) ? KS1 : KS0);
        const uint32_t* Vt = smu + ((kt & 1) ? VS1 : VS0);
        const int k0 = kt << 6;
        const bool act0 = (kt <= 2 * qt);

#pragma unroll
        for (int mt = 0; mt < 2; mt++) {
            if (mt == 0 && !act0) continue;

            // ---- S = Q K^T : K is d-permuted -> pair fragment = 1 LDS.64 ----
            float4 s[8];
#pragma unroll
            for (int nt = 0; nt < 8; nt++) s[nt] = make_float4(0.f, 0.f, 0.f, 0.f);
#pragma unroll
            for (int ks = 0; ks < 8; ks++) {
                const int kk2 = ks * 8 + t4 * 2;
#pragma unroll
                for (int nt = 0; nt < 8; nt++) {
                    uint2 bp = *(const uint2*)&Kt[(nt * 8 + g) * 72 + kk2];
                    mma8(s[nt], qa[mt][ks], bp.x, bp.y, s[nt]);
                }
            }

            // ---- causal mask ----
            if (kt >= 2 * qt) {
                int rowA = q0 + mt * 64 + wm * 16 + g;
#pragma unroll
                for (int nt = 0; nt < 8; nt++) {
                    int c0 = k0 + nt * 8 + 2 * t4;
                    if (c0     > rowA)     s[nt].x = NEG_INF;
                    if (c0 + 1 > rowA)     s[nt].y = NEG_INF;
                    if (c0     > rowA + 8) s[nt].z = NEG_INF;
                    if (c0 + 1 > rowA + 8) s[nt].w = NEG_INF;
                }
            }

            // ---- online softmax (base-2 domain) ----
            float mx0 = NEG_INF, mx1 = NEG_INF;
#pragma unroll
            for (int nt = 0; nt < 8; nt++) {
                mx0 = fmaxf(mx0, fmaxf(s[nt].x, s[nt].y));
                mx1 = fmaxf(mx1, fmaxf(s[nt].z, s[nt].w));
            }
            mx0 = fmaxf(mx0, __shfl_xor_sync(0xffffffffu, mx0, 1));
            mx0 = fmaxf(mx0, __shfl_xor_sync(0xffffffffu, mx0, 2));
            mx1 = fmaxf(mx1, __shfl_xor_sync(0xffffffffu, mx1, 1));
            mx1 = fmaxf(mx1, __shfl_xor_sync(0xffffffffu, mx1, 2));

            float mn0 = fmaxf(mrow[mt][0], mx0), mn1 = fmaxf(mrow[mt][1], mx1);
            float fac0 = ex2(mrow[mt][0] - mn0), fac1 = ex2(mrow[mt][1] - mn1);
            float sum0 = 0.f, sum1 = 0.f;
#pragma unroll
            for (int nt = 0; nt < 8; nt++) {
                s[nt].x = ex2(s[nt].x - mn0);
                s[nt].y = ex2(s[nt].y - mn0);
                s[nt].z = ex2(s[nt].z - mn1);
                s[nt].w = ex2(s[nt].w - mn1);
                sum0 += s[nt].x + s[nt].y;
                sum1 += s[nt].z + s[nt].w;
            }
            sum0 += __shfl_xor_sync(0xffffffffu, sum0, 1);
            sum0 += __shfl_xor_sync(0xffffffffu, sum0, 2);
            sum1 += __shfl_xor_sync(0xffffffffu, sum1, 1);
            sum1 += __shfl_xor_sync(0xffffffffu, sum1, 2);
            lrow[mt][0] = lrow[mt][0] * fac0 + sum0;
            lrow[mt][1] = lrow[mt][1] * fac1 + sum1;
            mrow[mt][0] = mn0; mrow[mt][1] = mn1;
#pragma unroll
            for (int dt = 0; dt < 8; dt++) {
                o[mt][dt].x *= fac0; o[mt][dt].y *= fac0;
                o[mt][dt].z *= fac1; o[mt][dt].w *= fac1;
            }

            // ---- store P (tf32, natural col order) ----
            {
                int pr = (mt * 64 + wm * 16 + g) * 72;
#pragma unroll
                for (int nt = 0; nt < 8; nt++) {
                    int c0 = nt * 8 + 2 * t4;
                    uint2 lo, hi;
                    lo.x = f2tf32(s[nt].x); lo.y = f2tf32(s[nt].y);
                    hi.x = f2tf32(s[nt].z); hi.y = f2tf32(s[nt].w);
                    *(uint2*)&Psm[pr + c0]          = lo;
                    *(uint2*)&Psm[pr + 8 * 72 + c0] = hi;
                }
            }
        }
        __syncwarp();   // P rows are private to this warp

        // ---- O += P V ----
#pragma unroll
        for (int ks = 0; ks < 8; ks++) {
            int kk = ks * 8 + t4;
            uint32_t pa[2][4];
#pragma unroll
            for (int mt = 0; mt < 2; mt++) {
                int pr = (mt * 64 + wm * 16 + g) * 72;
                pa[mt][0] = Psm[pr + kk];
                pa[mt][1] = Psm[pr + 8 * 72 + kk];
                pa[mt][2] = Psm[pr + kk + 4];
                pa[mt][3] = Psm[pr + 8 * 72 + kk + 4];
            }
#pragma unroll
            for (int dt = 0; dt < 8; dt++) {
                uint32_t b0 = Vt[kk * 72 + dt * 8 + g];
                uint32_t b1 = Vt[(kk + 4) * 72 + dt * 8 + g];
                if (act0) mma8(o[0][dt], pa[0], b0, b1, o[0][dt]);
                mma8(o[1][dt], pa[1], b0, b1, o[1][dt]);
            }
        }
    }

    // ---- epilogue: normalize, store PERMUTED tf32 bits (feeds O-gemm) ----
#pragma unroll
    for (int mt = 0; mt < 2; mt++) {
        float inv0 = 1.0f / lrow[mt][0], inv1 = 1.0f / lrow[mt][1];
        int r1 = q0 + mt * 64 + wm * 16 + g;
        int r2 = r1 + 8;
        size_t ro1 = ((size_t)(b * T_SZ) + r1) * D_MODEL;
        size_t ro2 = ((size_t)(b * T_SZ) + r2) * D_MODEL;
#pragma unroll
        for (int dt = 0; dt < 8; dt++) {
            int c0 = h * 64 + dt * 8 + 2 * t4;
            int p0 = kperm(c0), p1 = kperm(c0 + 1);
            Og[ro1 + p0] = f2tf32(o[mt][dt].x * inv0);
            Og[ro1 + p1] = f2tf32(o[mt][dt].y * inv0);
            Og[ro2 + p0] = f2tf32(o[mt][dt].z * inv1);
            Og[ro2 + p1] = f2tf32(o[mt][dt].w * inv1);
        }
    }
}

// ---------------------------------------------------------------------------
extern "C" void kernel_launch(void* const* d_in, const int* in_sizes, int n_in,
                              void* d_out, int out_size)
{
    const float* x_q  = (const float*)d_in[0];
    const float* x_kv = (const float*)d_in[1];
    const float* Wq   = (const float*)d_in[2];
    const float* Wk   = (const float*)d_in[3];
    const float* Wv   = (const float*)d_in[4];
    const float* Wo   = (const float*)d_in[5];
    float* out = (float*)d_out;

    uint32_t *pxq, *pxkv, *pwq, *pwk, *pwv, *pwo, *pq, *pk, *pv, *pattn;
    cudaGetSymbolAddress((void**)&pxq,  g_xq);
    cudaGetSymbolAddress((void**)&pxkv, g_xkv);
    cudaGetSymbolAddress((void**)&pwq,  g_wq);
    cudaGetSymbolAddress((void**)&pwk,  g_wk);
    cudaGetSymbolAddress((void**)&pwv,  g_wv);
    cudaGetSymbolAddress((void**)&pwo,  g_wo);
    cudaGetSymbolAddress((void**)&pq,   g_q);
    cudaGetSymbolAddress((void**)&pk,   g_k);
    cudaGetSymbolAddress((void**)&pv,   g_v);
    cudaGetSymbolAddress((void**)&pattn, g_attn);

    const int ATTN_SMEM = (18432 + 128 * 72) * 4;   // 110592 B
    const int GEMM_SMEM = 4 * 5120 * 4;             // 81920 B
    cudaFuncSetAttribute(attn_tc_kernel,
                         cudaFuncAttributeMaxDynamicSharedMemorySize, ATTN_SMEM);
    cudaFuncSetAttribute(gemm_qkv_kernel,
                         cudaFuncAttributeMaxDynamicSharedMemorySize, GEMM_SMEM);
    cudaFuncSetAttribute(gemm_o_kernel,
                         cudaFuncAttributeMaxDynamicSharedMemorySize, GEMM_SMEM);

    // ---- pre-convert + k-permute ALL inputs/weights in ONE launch ----
    CvtArgs ca;
    ca.src[0] = x_q;  ca.dst[0] = pxq;
    ca.src[1] = x_kv; ca.dst[1] = pxkv;
    ca.src[2] = Wq;   ca.dst[2] = pwq;
    ca.src[3] = Wk;   ca.dst[3] = pwk;
    ca.src[4] = Wv;   ca.dst[4] = pwv;
    ca.src[5] = Wo;   ca.dst[5] = pwo;
    cvtp_all_kernel<<<8192 + 4 * 512, 256>>>(ca);

    // ---- fused Q/K/V projections ----
    gemm_qkv_kernel<<<dim3(D_MODEL / 128, M_ROWS / 128, 3), 256, GEMM_SMEM>>>();

    // ---- attention ----
    attn_tc_kernel<<<dim3(T_SZ / 128, NUM_HEADS, B_SZ), 128, ATTN_SMEM>>>(pq, pk, pv, pattn);

    // ---- output projection ----
    gemm_o_kernel<<<dim3(D_MODEL / 128, M_ROWS / 128), 256, GEMM_SMEM>>>(out);
}

// round 15
// speedup vs baseline: 1.1137x; 1.1137x over previous
#include <cuda_runtime.h>
#include <cuda_fp16.h>
#include <cstdint>

#define D_MODEL   1024
#define NUM_HEADS 16
#define HEAD_DIM  64
#define B_SZ      4
#define T_SZ      2048
#define M_ROWS    (B_SZ * T_SZ)   // 8192

// Scratch (allocation-free rule: __device__ globals).
// GEMM operands: tf32 bits, k-PAIR-PERMUTED within 8-groups:
//   pos(k) = (k&~7) | ((k&3)<<1) | ((k>>2)&1)   (both operands -> bit-identical)
__device__ uint32_t g_xq [(size_t)M_ROWS * D_MODEL];     // permuted k
__device__ uint32_t g_xkv[(size_t)M_ROWS * D_MODEL];     // permuted k
__device__ uint32_t g_wq [(size_t)D_MODEL * D_MODEL];    // permuted k
__device__ uint32_t g_wk [(size_t)D_MODEL * D_MODEL];    // permuted k
__device__ uint32_t g_wv [(size_t)D_MODEL * D_MODEL];    // permuted k
__device__ uint32_t g_wo [(size_t)D_MODEL * D_MODEL];    // permuted k
__device__ uint32_t g_q  [(size_t)B_SZ * NUM_HEADS * T_SZ * HEAD_DIM];  // (b,h,t,d) tf32, pre-scaled 0.125*log2e
__device__ uint32_t g_k  [(size_t)B_SZ * NUM_HEADS * T_SZ * HEAD_DIM];  // (b,h,t,d) tf32, d k-pair-permuted
// V: fp16, layout (b,h,d,t): per d-row 1024 uint32 words (t-pairs), word-permuted
// within 8-word blocks: wpos(w) = (w&~7) | ((w&3)<<1) | ((w>>2)&1)
__device__ uint32_t g_v  [(size_t)B_SZ * NUM_HEADS * HEAD_DIM * (T_SZ / 2)];
__device__ uint32_t g_attn[(size_t)M_ROWS * D_MODEL];                   // tf32, permuted c

// ---------------------------------------------------------------------------
// helpers
// ---------------------------------------------------------------------------
__device__ __forceinline__ uint32_t f2tf32(float x) {
    uint32_t r;
    asm("cvt.rna.tf32.f32 %0, %1;" : "=r"(r) : "f"(x));
    return r;
}
__device__ __forceinline__ float ex2(float x) {
    float r;
    asm("ex2.approx.ftz.f32 %0, %1;" : "=f"(r) : "f"(x));
    return r;
}
__device__ __forceinline__ uint32_t f16x2pack(float hi, float lo) {   // lo -> bits[15:0]
    uint32_t r;
    asm("cvt.rn.f16x2.f32 %0, %1, %2;" : "=r"(r) : "f"(hi), "f"(lo));
    return r;
}
__device__ __forceinline__ int kperm(int c) {   // position of logical index c
    return (c & ~7) | ((c & 3) << 1) | ((c >> 2) & 1);
}

// D = A(16x8, row, tf32) * B(8x8, col, tf32) + C   (fp32 accum)
__device__ __forceinline__ void mma8(float4& d, const uint32_t* a,
                                     uint32_t b0, uint32_t b1, const float4& c) {
    asm volatile(
        "mma.sync.aligned.m16n8k8.row.col.f32.tf32.tf32.f32 "
        "{%0,%1,%2,%3}, {%4,%5,%6,%7}, {%8,%9}, {%10,%11,%12,%13};\n"
        : "=f"(d.x), "=f"(d.y), "=f"(d.z), "=f"(d.w)
        : "r"(a[0]), "r"(a[1]), "r"(a[2]), "r"(a[3]),
          "r"(b0), "r"(b1),
          "f"(c.x), "f"(c.y), "f"(c.z), "f"(c.w));
}

// D = A(16x16, row, f16) * B(16x8, col, f16) + C   (fp32 accum)
__device__ __forceinline__ void mma16h(float4& d, const uint32_t* a,
                                       uint32_t b0, uint32_t b1, const float4& c) {
    asm volatile(
        "mma.sync.aligned.m16n8k16.row.col.f32.f16.f16.f32 "
        "{%0,%1,%2,%3}, {%4,%5,%6,%7}, {%8,%9}, {%10,%11,%12,%13};\n"
        : "=f"(d.x), "=f"(d.y), "=f"(d.z), "=f"(d.w)
        : "r"(a[0]), "r"(a[1]), "r"(a[2]), "r"(a[3]),
          "r"(b0), "r"(b1),
          "f"(c.x), "f"(c.y), "f"(c.z), "f"(c.w));
}

__device__ __forceinline__ void cpa16(uint32_t s, const void* g) {
    asm volatile("cp.async.cg.shared.global [%0], [%1], 16;" :: "r"(s), "l"(g));
}
#define CP_COMMIT() asm volatile("cp.async.commit_group;")
#define CP_WAIT(n)  asm volatile("cp.async.wait_group %0;" :: "n"(n))

// ---------------------------------------------------------------------------
// Fused fp32 -> tf32 + k-pair permutation for ALL 6 arrays in ONE launch.
// ---------------------------------------------------------------------------
struct CvtArgs {
    const float* src[6];
    uint32_t*    dst[6];
};

__global__ __launch_bounds__(256)
void cvtp_all_kernel(CvtArgs args)
{
    int bid = blockIdx.x;
    int seg, off;
    if (bid < 8192) { seg = bid >> 12;        off = bid & 4095; }
    else            { seg = 2 + ((bid - 8192) >> 9); off = (bid - 8192) & 511; }
    const float* src = args.src[seg];
    uint32_t*    dst = args.dst[seg];
    size_t i = (size_t)off * 256 + threadIdx.x;
    const float* s = src + i * 8;
    float4 v0 = *(const float4*)s;
    float4 v1 = *(const float4*)(s + 4);
    uint4 o0, o1;
    o0.x = f2tf32(v0.x); o0.y = f2tf32(v1.x);
    o0.z = f2tf32(v0.y); o0.w = f2tf32(v1.y);
    o1.x = f2tf32(v0.z); o1.y = f2tf32(v1.z);
    o1.z = f2tf32(v0.w); o1.w = f2tf32(v1.w);
    *(uint4*)(dst + i * 8)     = o0;
    *(uint4*)(dst + i * 8 + 4) = o1;
}

// ---------------------------------------------------------------------------
// GEMM mainloop (R13 proven form): BM=BN=128, BK=32, 256 thr = 8 warps
// (2x4 of 64x32). Fragments via LDS.64 (pre-permuted k). Stride 40 words.
// Double-buffered cp.async, distance 2, two syncs per ktile.
// ---------------------------------------------------------------------------
#define GS 40
#define GEMM_MAIN(A_, W_)                                                      \
    extern __shared__ uint32_t smu[];                                          \
    const int tid  = threadIdx.x;                                              \
    const int lane = tid & 31;                                                 \
    const int w    = tid >> 5;                                                 \
    const int g    = lane >> 2;                                                \
    const int t4   = lane & 3;                                                 \
    const int wm   = (w >> 2) * 64;                                            \
    const int wn   = (w & 3) * 32;                                             \
    const int m0   = blockIdx.y << 7;                                          \
    const int n0   = blockIdx.x << 7;                                          \
    const uint32_t* Ap = (A_) + (size_t)m0 * D_MODEL;                          \
    const uint32_t* Wp = (W_) + (size_t)n0 * D_MODEL;                          \
    const uint32_t smb = (uint32_t)__cvta_generic_to_shared(smu);              \
    float4 acc[4][4];                                                          \
    for (int i = 0; i < 4; i++)                                                \
        for (int j = 0; j < 4; j++) acc[i][j] = make_float4(0.f,0.f,0.f,0.f);  \
    auto stage = [&](int kt, int buf) {                                        \
        uint32_t sA = smb + (uint32_t)(buf * 10240) * 4;                       \
        uint32_t sB = sA + 5120u * 4;                                          \
        _Pragma("unroll")                                                      \
        for (int i = 0; i < 4; i++) {                                          \
            int c  = tid + (i << 8);                                           \
            int r  = c >> 3;                                                   \
            int c8 = (c & 7) << 2;                                             \
            cpa16(sA + (uint32_t)(r * GS + c8) * 4,                            \
                  Ap + (size_t)r * D_MODEL + kt + c8);                         \
            cpa16(sB + (uint32_t)(r * GS + c8) * 4,                            \
                  Wp + (size_t)r * D_MODEL + kt + c8);                         \
        }                                                                      \
    };                                                                         \
    stage(0, 0);  CP_COMMIT();                                                 \
    stage(32, 1); CP_COMMIT();                                                 \
    for (int kti = 0; kti < 32; kti++) {                                       \
        if (kti < 31) { CP_WAIT(1); } else { CP_WAIT(0); }                     \
        __syncthreads();                                                       \
        const uint32_t* As = smu + (kti & 1) * 10240;                          \
        const uint32_t* Bs = As + 5120;                                        \
        _Pragma("unroll")                                                      \
        for (int ks = 0; ks < 4; ks++) {                                       \
            const int kk2 = ks * 8 + t4 * 2;                                   \
            uint32_t a[4][4], bb[4][2];                                        \
            _Pragma("unroll")                                                  \
            for (int mt = 0; mt < 4; mt++) {                                   \
                int m = wm + mt * 16 + g;                                      \
                uint2 u = *(const uint2*)&As[m * GS + kk2];                    \
                uint2 v = *(const uint2*)&As[(m + 8) * GS + kk2];              \
                a[mt][0] = u.x; a[mt][1] = v.x;                                \
                a[mt][2] = u.y; a[mt][3] = v.y;                                \
            }                                                                  \
            _Pragma("unroll")                                                  \
            for (int nt = 0; nt < 4; nt++) {                                   \
                int n = wn + nt * 8 + g;                                       \
                uint2 p = *(const uint2*)&Bs[n * GS + kk2];                    \
                bb[nt][0] = p.x; bb[nt][1] = p.y;                              \
            }                                                                  \
            _Pragma("unroll")                                                  \
            for (int mt = 0; mt < 4; mt++)                                     \
                _Pragma("unroll")                                              \
                for (int nt = 0; nt < 4; nt++)                                 \
                    mma8(acc[mt][nt], a[mt], bb[nt][0], bb[nt][1], acc[mt][nt]);\
        }                                                                      \
        __syncthreads();                                                       \
        if (kti + 2 < 32) { stage((kti + 2) << 5, kti & 1); CP_COMMIT(); }     \
    }

// ---------------------------------------------------------------------------
// Fused Q/K/V projection. Q: tf32 natural d (scaled 0.125*log2e).
// K: tf32, d k-pair-permuted. V: fp16, (b,h,d,t) with 8-word t-block perm.
// ---------------------------------------------------------------------------
__global__ __launch_bounds__(256, 2)
void gemm_qkv_kernel()
{
    const uint32_t* Asel; const uint32_t* Wsel; float scale = 1.0f;
    if (blockIdx.z == 0)      { Asel = g_xq;  Wsel = g_wq; scale = 0.18033688011112042f; }
    else if (blockIdx.z == 1) { Asel = g_xkv; Wsel = g_wk; }
    else                      { Asel = g_xkv; Wsel = g_wv; }

    GEMM_MAIN(Asel, Wsel)

#pragma unroll
    for (int mt = 0; mt < 4; mt++) {
        int r1 = m0 + wm + mt * 16 + g;
        int r2 = r1 + 8;
        int b1 = r1 >> 11, t1 = r1 & 2047;
        int b2 = r2 >> 11, t2 = r2 & 2047;
#pragma unroll
        for (int nt = 0; nt < 4; nt++) {
            int c0 = n0 + wn + nt * 8 + 2 * t4;
            int hh = c0 >> 6, d0 = c0 & 63;
            if (blockIdx.z == 2) {
                // V: fp16 scatter to (b,h,d,t), t word-permuted
                __half* Vh = (__half*)g_v;
                auto storeV = [&](int bb, int t, int d, float val) {
                    int wrd  = t >> 1;
                    int widx = (wrd & ~7) | ((wrd & 3) << 1) | ((wrd >> 2) & 1);
                    size_t hi = (((size_t)bb * NUM_HEADS + hh) * HEAD_DIM + d) * (size_t)T_SZ
                              + (size_t)widx * 2 + (t & 1);
                    Vh[hi] = __float2half_rn(val);
                };
                storeV(b1, t1, d0,     acc[mt][nt].x);
                storeV(b1, t1, d0 + 1, acc[mt][nt].y);
                storeV(b2, t2, d0,     acc[mt][nt].z);
                storeV(b2, t2, d0 + 1, acc[mt][nt].w);
            } else {
                uint32_t* Csel = (blockIdx.z == 0) ? g_q : g_k;
                uint32_t q00 = f2tf32(acc[mt][nt].x * scale);
                uint32_t q01 = f2tf32(acc[mt][nt].y * scale);
                uint32_t q10 = f2tf32(acc[mt][nt].z * scale);
                uint32_t q11 = f2tf32(acc[mt][nt].w * scale);
                size_t base1 = (((size_t)b1 * NUM_HEADS + hh) * T_SZ + t1) * HEAD_DIM;
                size_t base2 = (((size_t)b2 * NUM_HEADS + hh) * T_SZ + t2) * HEAD_DIM;
                if (blockIdx.z == 1) {
                    int p0 = kperm(d0), p1 = kperm(d0 + 1);
                    Csel[base1 + p0] = q00;  Csel[base1 + p1] = q01;
                    Csel[base2 + p0] = q10;  Csel[base2 + p1] = q11;
                } else {
                    *(uint2*)&Csel[base1 + d0] = make_uint2(q00, q01);
                    *(uint2*)&Csel[base2 + d0] = make_uint2(q10, q11);
                }
            }
        }
    }
}

// ---------------------------------------------------------------------------
// Output projection: A = g_attn (permuted c), W = g_wo (permuted k), C fp32.
// ---------------------------------------------------------------------------
__global__ __launch_bounds__(256, 2)
void gemm_o_kernel(float* __restrict__ C)
{
    GEMM_MAIN(g_attn, g_wo)

#pragma unroll
    for (int mt = 0; mt < 4; mt++) {
        int r1 = m0 + wm + mt * 16 + g;
        int r2 = r1 + 8;
#pragma unroll
        for (int nt = 0; nt < 4; nt++) {
            int c0 = n0 + wn + nt * 8 + 2 * t4;
            *(float2*)&C[(size_t)r1 * D_MODEL + c0] =
                make_float2(acc[mt][nt].x, acc[mt][nt].y);
            *(float2*)&C[(size_t)r2 * D_MODEL + c0] =
                make_float2(acc[mt][nt].z, acc[mt][nt].w);
        }
    }
}

// ---------------------------------------------------------------------------
// Causal flash attention. S = QK^T in tf32 (K d-permuted, LDS.64 frags,
// hoisted across mt). Softmax base-2. P packed to fp16 IN REGISTERS (the
// m16n8k16.f16 A-fragment == softmaxed C-fragment layout) -> no P smem.
// PV in fp16 mma k16 (half the mma count); V fp16 (b,h,d,t) staged to smem
// stride 40 words, fragments = conflict-free LDS.64.
// Smem (words): K0@0 K1@4608 V0@9216 V1@11776 ; total 14336 w = 57344 B.
// ---------------------------------------------------------------------------
__global__ __launch_bounds__(128, 2)
void attn_tc_kernel(const uint32_t* __restrict__ Qg, const uint32_t* __restrict__ Kg,
                    const uint32_t* __restrict__ Vg, uint32_t* __restrict__ Og)
{
    extern __shared__ uint32_t smu[];
    const int KS0 = 0, KS1 = 4608, VS0 = 9216, VS1 = 11776;

    const int tid  = threadIdx.x;
    const int lane = tid & 31;
    const int wm   = tid >> 5;
    const int g    = lane >> 2;
    const int t4   = lane & 3;
    const int qt   = (int)(gridDim.x - 1) - (int)blockIdx.x;  // long blocks first
    const int q0   = qt << 7;
    const int h    = blockIdx.y;
    const int b    = blockIdx.z;

    const size_t base  = ((size_t)(b * NUM_HEADS + h)) * T_SZ * HEAD_DIM;
    const size_t vbase = ((size_t)(b * NUM_HEADS + h)) * HEAD_DIM * (T_SZ / 2);
    const uint32_t smb = (uint32_t)__cvta_generic_to_shared(smu);
    const float NEG_INF = __int_as_float(0xff800000);

    // ---- stage Q (tf32, pre-scaled): rows 0-63 -> KS0, rows 64-127 -> KS1 ----
    {
        const uint32_t* Qp = Qg + base + (size_t)q0 * HEAD_DIM;
#pragma unroll
        for (int i = 0; i < 16; i++) {
            int c  = tid + (i << 7);
            int r  = c >> 4;
            int c4 = (c & 15) << 2;
            int off = (r < 64) ? (KS0 + r * 72 + c4) : (KS1 + (r - 64) * 72 + c4);
            cpa16(smb + (uint32_t)off * 4, Qp + r * 64 + c4);
        }
    }
    CP_COMMIT(); CP_WAIT(0);
    __syncthreads();

    // ---- Q fragments -> registers ----
    uint32_t qa[2][8][4];
#pragma unroll
    for (int mt = 0; mt < 2; mt++) {
        const uint32_t* Qs = smu + (mt ? KS1 : KS0);
        const int row = wm * 16 + g;
#pragma unroll
        for (int ks = 0; ks < 8; ks++) {
            int kk = ks * 8 + t4;
            qa[mt][ks][0] = Qs[row * 72 + kk];
            qa[mt][ks][1] = Qs[(row + 8) * 72 + kk];
            qa[mt][ks][2] = Qs[row * 72 + kk + 4];
            qa[mt][ks][3] = Qs[(row + 8) * 72 + kk + 4];
        }
    }
    __syncthreads();

    auto stageKV = [&](int kt, int buf) {
        const uint32_t* Kp = Kg + base + (size_t)(kt << 6) * HEAD_DIM;
        const uint32_t* Vp = Vg + vbase + (kt << 5);      // 32 words per 64-t window
        const int ko = buf ? KS1 : KS0;
        const int vo = buf ? VS1 : VS0;
#pragma unroll
        for (int i = 0; i < 8; i++) {
            int c  = tid + (i << 7);
            int r  = c >> 4;
            int c4 = (c & 15) << 2;
            cpa16(smb + (uint32_t)(ko + r * 72 + c4) * 4, Kp + r * 64 + c4);
        }
#pragma unroll
        for (int i = 0; i < 4; i++) {
            int c  = tid + (i << 7);
            int r  = c >> 3;                 // d-row 0..63
            int c4 = (c & 7) << 2;           // 0..28
            cpa16(smb + (uint32_t)(vo + r * 40 + c4) * 4,
                  Vp + (size_t)r * (T_SZ / 2) + c4);
        }
    };

    stageKV(0, 0); CP_COMMIT();

    float4 o[2][8];
#pragma unroll
    for (int mt = 0; mt < 2; mt++)
#pragma unroll
        for (int dt = 0; dt < 8; dt++) o[mt][dt] = make_float4(0.f, 0.f, 0.f, 0.f);
    float mrow[2][2] = {{NEG_INF, NEG_INF}, {NEG_INF, NEG_INF}};
    float lrow[2][2] = {{0.f, 0.f}, {0.f, 0.f}};

    const int nkt = 2 * qt + 2;
    for (int kt = 0; kt < nkt; kt++) {
        if (kt + 1 < nkt) { stageKV(kt + 1, (kt + 1) & 1); CP_COMMIT(); CP_WAIT(1); }
        else              { CP_WAIT(0); }
        __syncthreads();

        const uint32_t* Kt = smu + ((kt & 1) ? KS1 : KS0);
        const uint32_t* Vt = smu + ((kt & 1) ? VS1 : VS0);
        const int k0 = kt << 6;
        const bool act0 = (kt <= 2 * qt);   // mt0 fully masked on last tile

        // ---- S = Q K^T : K fragments hoisted across both m-tiles ----
        float4 s[2][8];
#pragma unroll
        for (int mt = 0; mt < 2; mt++)
#pragma unroll
            for (int nt = 0; nt < 8; nt++) s[mt][nt] = make_float4(0.f, 0.f, 0.f, 0.f);
#pragma unroll
        for (int nt = 0; nt < 8; nt++) {
            const int rowb = (nt * 8 + g) * 72;
#pragma unroll
            for (int ks = 0; ks < 8; ks++) {
                uint2 bp = *(const uint2*)&Kt[rowb + ks * 8 + 2 * t4];
                if (act0) mma8(s[0][nt], qa[0][ks], bp.x, bp.y, s[0][nt]);
                mma8(s[1][nt], qa[1][ks], bp.x, bp.y, s[1][nt]);
            }
        }

        // ---- causal mask ----
        if (kt >= 2 * qt) {
#pragma unroll
            for (int mt = 0; mt < 2; mt++) {
                if (mt == 0 && !act0) continue;
                int rowA = q0 + mt * 64 + wm * 16 + g;
#pragma unroll
                for (int nt = 0; nt < 8; nt++) {
                    int c0 = k0 + nt * 8 + 2 * t4;
                    if (c0     > rowA)     s[mt][nt].x = NEG_INF;
                    if (c0 + 1 > rowA)     s[mt][nt].y = NEG_INF;
                    if (c0     > rowA + 8) s[mt][nt].z = NEG_INF;
                    if (c0 + 1 > rowA + 8) s[mt][nt].w = NEG_INF;
                }
            }
        }

        // ---- online softmax (base-2) + pack P to fp16 A-fragments ----
        uint32_t pa[2][4][4];
#pragma unroll
        for (int mt = 0; mt < 2; mt++) {
            if (mt == 0 && !act0) continue;
            float mx0 = NEG_INF, mx1 = NEG_INF;
#pragma unroll
            for (int nt = 0; nt < 8; nt++) {
                mx0 = fmaxf(mx0, fmaxf(s[mt][nt].x, s[mt][nt].y));
                mx1 = fmaxf(mx1, fmaxf(s[mt][nt].z, s[mt][nt].w));
            }
            mx0 = fmaxf(mx0, __shfl_xor_sync(0xffffffffu, mx0, 1));
            mx0 = fmaxf(mx0, __shfl_xor_sync(0xffffffffu, mx0, 2));
            mx1 = fmaxf(mx1, __shfl_xor_sync(0xffffffffu, mx1, 1));
            mx1 = fmaxf(mx1, __shfl_xor_sync(0xffffffffu, mx1, 2));

            float mn0 = fmaxf(mrow[mt][0], mx0), mn1 = fmaxf(mrow[mt][1], mx1);
            float fac0 = ex2(mrow[mt][0] - mn0), fac1 = ex2(mrow[mt][1] - mn1);
            float sum0 = 0.f, sum1 = 0.f;
#pragma unroll
            for (int nt = 0; nt < 8; nt++) {
                s[mt][nt].x = ex2(s[mt][nt].x - mn0);
                s[mt][nt].y = ex2(s[mt][nt].y - mn0);
                s[mt][nt].z = ex2(s[mt][nt].z - mn1);
                s[mt][nt].w = ex2(s[mt][nt].w - mn1);
                sum0 += s[mt][nt].x + s[mt][nt].y;
                sum1 += s[mt][nt].z + s[mt][nt].w;
            }
            sum0 += __shfl_xor_sync(0xffffffffu, sum0, 1);
            sum0 += __shfl_xor_sync(0xffffffffu, sum0, 2);
            sum1 += __shfl_xor_sync(0xffffffffu, sum1, 1);
            sum1 += __shfl_xor_sync(0xffffffffu, sum1, 2);
            lrow[mt][0] = lrow[mt][0] * fac0 + sum0;
            lrow[mt][1] = lrow[mt][1] * fac1 + sum1;
            mrow[mt][0] = mn0; mrow[mt][1] = mn1;
#pragma unroll
            for (int dt = 0; dt < 8; dt++) {
                o[mt][dt].x *= fac0; o[mt][dt].y *= fac0;
                o[mt][dt].z *= fac1; o[mt][dt].w *= fac1;
            }
            // pack: a0=(row g, k lo-pair), a1=(row g+8, lo), a2=(g, hi), a3=(g+8, hi)
#pragma unroll
            for (int kp = 0; kp < 4; kp++) {
                pa[mt][kp][0] = f16x2pack(s[mt][2 * kp].y,     s[mt][2 * kp].x);
                pa[mt][kp][1] = f16x2pack(s[mt][2 * kp].w,     s[mt][2 * kp].z);
                pa[mt][kp][2] = f16x2pack(s[mt][2 * kp + 1].y, s[mt][2 * kp + 1].x);
                pa[mt][kp][3] = f16x2pack(s[mt][2 * kp + 1].w, s[mt][2 * kp + 1].z);
            }
        }

        // ---- O += P V  (fp16 k16 mma; V fragments one LDS.64 each) ----
#pragma unroll
        for (int kp = 0; kp < 4; kp++) {
#pragma unroll
            for (int dt = 0; dt < 8; dt++) {
                uint2 vv = *(const uint2*)&Vt[(dt * 8 + g) * 40 + kp * 8 + 2 * t4];
                if (act0) mma16h(o[0][dt], pa[0][kp], vv.x, vv.y, o[0][dt]);
                mma16h(o[1][dt], pa[1][kp], vv.x, vv.y, o[1][dt]);
            }
        }
        __syncthreads();   // all reads of this stage's K/V done before overwrite
    }

    // ---- epilogue: normalize, store PERMUTED tf32 bits (feeds O-gemm) ----
#pragma unroll
    for (int mt = 0; mt < 2; mt++) {
        float inv0 = 1.0f / lrow[mt][0], inv1 = 1.0f / lrow[mt][1];
        int r1 = q0 + mt * 64 + wm * 16 + g;
        int r2 = r1 + 8;
        size_t ro1 = ((size_t)(b * T_SZ) + r1) * D_MODEL;
        size_t ro2 = ((size_t)(b * T_SZ) + r2) * D_MODEL;
#pragma unroll
        for (int dt = 0; dt < 8; dt++) {
            int c0 = h * 64 + dt * 8 + 2 * t4;
            int p0 = kperm(c0), p1 = kperm(c0 + 1);
            Og[ro1 + p0] = f2tf32(o[mt][dt].x * inv0);
            Og[ro1 + p1] = f2tf32(o[mt][dt].y * inv0);
            Og[ro2 + p0] = f2tf32(o[mt][dt].z * inv1);
            Og[ro2 + p1] = f2tf32(o[mt][dt].w * inv1);
        }
    }
}

// ---------------------------------------------------------------------------
extern "C" void kernel_launch(void* const* d_in, const int* in_sizes, int n_in,
                              void* d_out, int out_size)
{
    const float* x_q  = (const float*)d_in[0];
    const float* x_kv = (const float*)d_in[1];
    const float* Wq   = (const float*)d_in[2];
    const float* Wk   = (const float*)d_in[3];
    const float* Wv   = (const float*)d_in[4];
    const float* Wo   = (const float*)d_in[5];
    float* out = (float*)d_out;

    uint32_t *pxq, *pxkv, *pwq, *pwk, *pwv, *pwo, *pq, *pk, *pv, *pattn;
    cudaGetSymbolAddress((void**)&pxq,  g_xq);
    cudaGetSymbolAddress((void**)&pxkv, g_xkv);
    cudaGetSymbolAddress((void**)&pwq,  g_wq);
    cudaGetSymbolAddress((void**)&pwk,  g_wk);
    cudaGetSymbolAddress((void**)&pwv,  g_wv);
    cudaGetSymbolAddress((void**)&pwo,  g_wo);
    cudaGetSymbolAddress((void**)&pq,   g_q);
    cudaGetSymbolAddress((void**)&pk,   g_k);
    cudaGetSymbolAddress((void**)&pv,   g_v);
    cudaGetSymbolAddress((void**)&pattn, g_attn);

    const int ATTN_SMEM = 14336 * 4;                // 57344 B
    const int GEMM_SMEM = 4 * 5120 * 4;             // 81920 B
    cudaFuncSetAttribute(attn_tc_kernel,
                         cudaFuncAttributeMaxDynamicSharedMemorySize, ATTN_SMEM);
    cudaFuncSetAttribute(gemm_qkv_kernel,
                         cudaFuncAttributeMaxDynamicSharedMemorySize, GEMM_SMEM);
    cudaFuncSetAttribute(gemm_o_kernel,
                         cudaFuncAttributeMaxDynamicSharedMemorySize, GEMM_SMEM);

    // ---- pre-convert + k-permute ALL inputs/weights in ONE launch ----
    CvtArgs ca;
    ca.src[0] = x_q;  ca.dst[0] = pxq;
    ca.src[1] = x_kv; ca.dst[1] = pxkv;
    ca.src[2] = Wq;   ca.dst[2] = pwq;
    ca.src[3] = Wk;   ca.dst[3] = pwk;
    ca.src[4] = Wv;   ca.dst[4] = pwv;
    ca.src[5] = Wo;   ca.dst[5] = pwo;
    cvtp_all_kernel<<<8192 + 4 * 512, 256>>>(ca);

    // ---- fused Q/K/V projections ----
    gemm_qkv_kernel<<<dim3(D_MODEL / 128, M_ROWS / 128, 3), 256, GEMM_SMEM>>>();

    // ---- attention ----
    attn_tc_kernel<<<dim3(T_SZ / 128, NUM_HEADS, B_SZ), 128, ATTN_SMEM>>>(pq, pk, pv, pattn);

    // ---- output projection ----
    gemm_o_kernel<<<dim3(D_MODEL / 128, M_ROWS / 128), 256, GEMM_SMEM>>>(out);
}

// round 16
// speedup vs baseline: 1.8781x; 1.6863x over previous
#include <cuda_runtime.h>
#include <cuda_fp16.h>
#include <cstdint>

#define D_MODEL   1024
#define NUM_HEADS 16
#define HEAD_DIM  64
#define B_SZ      4
#define T_SZ      2048
#define M_ROWS    (B_SZ * T_SZ)   // 8192
#define DW        (D_MODEL / 2)   // 512 fp16x2 words per row

// Scratch (allocation-free rule: __device__ globals). All fp16x2 words.
// Contraction-dim words are PAIR-PERMUTED within 8-word groups:
//   wpos(w) = (w&~7) | ((w&3)<<1) | ((w>>2)&1)
// Both operands of every mma share the permutation -> pairings consistent.
__device__ uint32_t g_xq [(size_t)M_ROWS * DW];          // k-words permuted
__device__ uint32_t g_xkv[(size_t)M_ROWS * DW];          // k-words permuted
__device__ uint32_t g_wq [(size_t)D_MODEL * DW];         // k-words permuted
__device__ uint32_t g_wk [(size_t)D_MODEL * DW];         // k-words permuted
__device__ uint32_t g_wv [(size_t)D_MODEL * DW];         // k-words permuted
__device__ uint32_t g_wo [(size_t)D_MODEL * DW];         // k-words permuted
__device__ uint32_t g_q  [(size_t)B_SZ * NUM_HEADS * T_SZ * 32];  // (b,h,t,dw) perm, pre-scaled 0.125*log2e
__device__ uint32_t g_k  [(size_t)B_SZ * NUM_HEADS * T_SZ * 32];  // (b,h,t,dw) perm
__device__ uint32_t g_v  [(size_t)B_SZ * NUM_HEADS * HEAD_DIM * (T_SZ / 2)];  // (b,h,d,tw) perm
__device__ uint32_t g_attn[(size_t)M_ROWS * DW];         // c-words permuted

// ---------------------------------------------------------------------------
// helpers
// ---------------------------------------------------------------------------
__device__ __forceinline__ float ex2(float x) {
    float r;
    asm("ex2.approx.ftz.f32 %0, %1;" : "=f"(r) : "f"(x));
    return r;
}
__device__ __forceinline__ uint32_t f16x2pack(float hi, float lo) {   // lo -> bits[15:0]
    uint32_t r;
    asm("cvt.rn.f16x2.f32 %0, %1, %2;" : "=r"(r) : "f"(hi), "f"(lo));
    return r;
}
__device__ __forceinline__ int wperm(int w) {   // position of logical word w
    return (w & ~7) | ((w & 3) << 1) | ((w >> 2) & 1);
}

// D = A(16x16, row, f16) * B(16x8, col, f16) + C   (fp32 accum)
__device__ __forceinline__ void mma16h(float4& d, const uint32_t* a,
                                       uint32_t b0, uint32_t b1, const float4& c) {
    asm volatile(
        "mma.sync.aligned.m16n8k16.row.col.f32.f16.f16.f32 "
        "{%0,%1,%2,%3}, {%4,%5,%6,%7}, {%8,%9}, {%10,%11,%12,%13};\n"
        : "=f"(d.x), "=f"(d.y), "=f"(d.z), "=f"(d.w)
        : "r"(a[0]), "r"(a[1]), "r"(a[2]), "r"(a[3]),
          "r"(b0), "r"(b1),
          "f"(c.x), "f"(c.y), "f"(c.z), "f"(c.w));
}

__device__ __forceinline__ void cpa16(uint32_t s, const void* g) {
    asm volatile("cp.async.cg.shared.global [%0], [%1], 16;" :: "r"(s), "l"(g));
}
#define CP_COMMIT() asm volatile("cp.async.commit_group;")
#define CP_WAIT(n)  asm volatile("cp.async.wait_group %0;" :: "n"(n))

// ---------------------------------------------------------------------------
// Fused fp32 -> fp16x2 + word-pair permutation, ALL 6 arrays in ONE launch.
// Thread handles 16 consecutive floats -> 8 words {w0,w4,w1,w5,w2,w6,w3,w7}.
// ---------------------------------------------------------------------------
struct CvtArgs {
    const float* src[6];
    uint32_t*    dst[6];
};

__global__ __launch_bounds__(256)
void cvtp_all_kernel(CvtArgs args)
{
    int bid = blockIdx.x;
    int seg, off;
    if (bid < 4096) { seg = bid >> 11;               off = bid & 2047; }
    else            { seg = 2 + ((bid - 4096) >> 8); off = (bid - 4096) & 255; }
    const float* src = args.src[seg];
    uint32_t*    dst = args.dst[seg];
    size_t i = (size_t)off * 256 + threadIdx.x;
    const float* s = src + i * 16;
    float4 v0 = *(const float4*)s;
    float4 v1 = *(const float4*)(s + 4);
    float4 v2 = *(const float4*)(s + 8);
    float4 v3 = *(const float4*)(s + 12);
    uint32_t w0 = f16x2pack(v0.y, v0.x);   // logical word 0
    uint32_t w1 = f16x2pack(v0.w, v0.z);
    uint32_t w2 = f16x2pack(v1.y, v1.x);
    uint32_t w3 = f16x2pack(v1.w, v1.z);
    uint32_t w4 = f16x2pack(v2.y, v2.x);
    uint32_t w5 = f16x2pack(v2.w, v2.z);
    uint32_t w6 = f16x2pack(v3.y, v3.x);
    uint32_t w7 = f16x2pack(v3.w, v3.z);
    uint4 o0 = make_uint4(w0, w4, w1, w5);   // positions 0..3
    uint4 o1 = make_uint4(w2, w6, w3, w7);   // positions 4..7
    *(uint4*)(dst + i * 8)     = o0;
    *(uint4*)(dst + i * 8 + 4) = o1;
}

// ---------------------------------------------------------------------------
// fp16 GEMM mainloop: BM=BN=128, BK=64 (32 words), 256 thr = 8 warps
// (2x4 of 64x32 warp tiles), m16n8k16. Fragments = LDS.64 (word-pair perm).
// Stride 40 words (conflict-free 8g+2t4). Double-buffered cp.async, dist 2.
// 16 ktiles. Smem: 4 x 5120 words = 80KB.
// ---------------------------------------------------------------------------
#define GS 40
#define GEMM_MAIN(A_, W_)                                                      \
    extern __shared__ uint32_t smu[];                                          \
    const int tid  = threadIdx.x;                                              \
    const int lane = tid & 31;                                                 \
    const int w    = tid >> 5;                                                 \
    const int g    = lane >> 2;                                                \
    const int t4   = lane & 3;                                                 \
    const int wm   = (w >> 2) * 64;                                            \
    const int wn   = (w & 3) * 32;                                             \
    const int m0   = blockIdx.y << 7;                                          \
    const int n0   = blockIdx.x << 7;                                          \
    const uint32_t* Ap = (A_) + (size_t)m0 * DW;                               \
    const uint32_t* Wp = (W_) + (size_t)n0 * DW;                               \
    const uint32_t smb = (uint32_t)__cvta_generic_to_shared(smu);              \
    float4 acc[4][4];                                                          \
    for (int i = 0; i < 4; i++)                                                \
        for (int j = 0; j < 4; j++) acc[i][j] = make_float4(0.f,0.f,0.f,0.f);  \
    auto stage = [&](int ktw, int buf) {                                       \
        uint32_t sA = smb + (uint32_t)(buf * 10240) * 4;                       \
        uint32_t sB = sA + 5120u * 4;                                          \
        _Pragma("unroll")                                                      \
        for (int i = 0; i < 4; i++) {                                          \
            int c  = tid + (i << 8);          /* 0..1023 */                    \
            int r  = c >> 3;                                                   \
            int c8 = (c & 7) << 2;                                             \
            cpa16(sA + (uint32_t)(r * GS + c8) * 4,                            \
                  Ap + (size_t)r * DW + ktw + c8);                             \
            cpa16(sB + (uint32_t)(r * GS + c8) * 4,                            \
                  Wp + (size_t)r * DW + ktw + c8);                             \
        }                                                                      \
    };                                                                         \
    stage(0, 0);  CP_COMMIT();                                                 \
    stage(32, 1); CP_COMMIT();                                                 \
    for (int kti = 0; kti < 16; kti++) {                                       \
        if (kti < 15) { CP_WAIT(1); } else { CP_WAIT(0); }                     \
        __syncthreads();                                                       \
        const uint32_t* As = smu + (kti & 1) * 10240;                          \
        const uint32_t* Bs = As + 5120;                                        \
        _Pragma("unroll")                                                      \
        for (int ks = 0; ks < 4; ks++) {                                       \
            const int kk2 = ks * 8 + t4 * 2;                                   \
            uint32_t a[4][4], bb[4][2];                                        \
            _Pragma("unroll")                                                  \
            for (int mt = 0; mt < 4; mt++) {                                   \
                int m = wm + mt * 16 + g;                                      \
                uint2 u = *(const uint2*)&As[m * GS + kk2];                    \
                uint2 v = *(const uint2*)&As[(m + 8) * GS + kk2];              \
                a[mt][0] = u.x; a[mt][1] = v.x;                                \
                a[mt][2] = u.y; a[mt][3] = v.y;                                \
            }                                                                  \
            _Pragma("unroll")                                                  \
            for (int nt = 0; nt < 4; nt++) {                                   \
                int n = wn + nt * 8 + g;                                       \
                uint2 p = *(const uint2*)&Bs[n * GS + kk2];                    \
                bb[nt][0] = p.x; bb[nt][1] = p.y;                              \
            }                                                                  \
            _Pragma("unroll")                                                  \
            for (int mt = 0; mt < 4; mt++)                                     \
                _Pragma("unroll")                                              \
                for (int nt = 0; nt < 4; nt++)                                 \
                    mma16h(acc[mt][nt], a[mt], bb[nt][0], bb[nt][1], acc[mt][nt]);\
        }                                                                      \
        __syncthreads();                                                       \
        if (kti + 2 < 16) { stage((kti + 2) << 5, kti & 1); CP_COMMIT(); }     \
    }

// ---------------------------------------------------------------------------
// Fused Q/K/V projection. Q/K: fp16x2 (b,h,t,dw) word-permuted
// (Q pre-scaled by 0.125*log2e). V: fp16 (b,h,d,t) with t-word perm.
// ---------------------------------------------------------------------------
__global__ __launch_bounds__(256, 2)
void gemm_qkv_kernel()
{
    const uint32_t* Asel; const uint32_t* Wsel; float scale = 1.0f;
    if (blockIdx.z == 0)      { Asel = g_xq;  Wsel = g_wq; scale = 0.18033688011112042f; }
    else if (blockIdx.z == 1) { Asel = g_xkv; Wsel = g_wk; }
    else                      { Asel = g_xkv; Wsel = g_wv; }

    GEMM_MAIN(Asel, Wsel)

#pragma unroll
    for (int mt = 0; mt < 4; mt++) {
        int r1 = m0 + wm + mt * 16 + g;
        int r2 = r1 + 8;
        int b1 = r1 >> 11, t1 = r1 & 2047;
        int b2 = r2 >> 11, t2 = r2 & 2047;
#pragma unroll
        for (int nt = 0; nt < 4; nt++) {
            int c0 = n0 + wn + nt * 8 + 2 * t4;
            int hh = c0 >> 6, d0 = c0 & 63;
            if (blockIdx.z == 2) {
                // V: fp16 scatter to (b,h,d,t), t word-permuted
                __half* Vh = (__half*)g_v;
                auto storeV = [&](int bb, int t, int d, float val) {
                    int wrd  = t >> 1;
                    int widx = (wrd & ~7) | ((wrd & 3) << 1) | ((wrd >> 2) & 1);
                    size_t hi = (((size_t)bb * NUM_HEADS + hh) * HEAD_DIM + d) * (size_t)T_SZ
                              + (size_t)widx * 2 + (t & 1);
                    Vh[hi] = __float2half_rn(val);
                };
                storeV(b1, t1, d0,     acc[mt][nt].x);
                storeV(b1, t1, d0 + 1, acc[mt][nt].y);
                storeV(b2, t2, d0,     acc[mt][nt].z);
                storeV(b2, t2, d0 + 1, acc[mt][nt].w);
            } else {
                uint32_t* Csel = (blockIdx.z == 0) ? g_q : g_k;
                int dw = d0 >> 1;                 // word index within head (0..31)
                int pw = wperm(dw);
                size_t base1 = (((size_t)b1 * NUM_HEADS + hh) * T_SZ + t1) * 32;
                size_t base2 = (((size_t)b2 * NUM_HEADS + hh) * T_SZ + t2) * 32;
                Csel[base1 + pw] = f16x2pack(acc[mt][nt].y * scale, acc[mt][nt].x * scale);
                Csel[base2 + pw] = f16x2pack(acc[mt][nt].w * scale, acc[mt][nt].z * scale);
            }
        }
    }
}

// ---------------------------------------------------------------------------
// Output projection: A = g_attn, W = g_wo (both fp16x2 word-perm), C fp32.
// ---------------------------------------------------------------------------
__global__ __launch_bounds__(256, 2)
void gemm_o_kernel(float* __restrict__ C)
{
    GEMM_MAIN(g_attn, g_wo)

#pragma unroll
    for (int mt = 0; mt < 4; mt++) {
        int r1 = m0 + wm + mt * 16 + g;
        int r2 = r1 + 8;
#pragma unroll
        for (int nt = 0; nt < 4; nt++) {
            int c0 = n0 + wn + nt * 8 + 2 * t4;
            *(float2*)&C[(size_t)r1 * D_MODEL + c0] =
                make_float2(acc[mt][nt].x, acc[mt][nt].y);
            *(float2*)&C[(size_t)r2 * D_MODEL + c0] =
                make_float2(acc[mt][nt].z, acc[mt][nt].w);
        }
    }
}

// ---------------------------------------------------------------------------
// Causal flash attention, ALL fp16 mma (k16). S = QK^T with Q frags resident
// (word-perm -> LDS.64); softmax base-2; P packed fp16 in registers; PV fp16.
// Smem (words): K0@0 K1@2560 V0@5120 V1@7680; total 10240 w = 40960 B.
// Q staged into K0/K1 (rows 0-63 / 64-127) before the mainloop.
// ---------------------------------------------------------------------------
__global__ __launch_bounds__(128, 2)
void attn_tc_kernel(const uint32_t* __restrict__ Qg, const uint32_t* __restrict__ Kg,
                    const uint32_t* __restrict__ Vg, uint32_t* __restrict__ Og)
{
    extern __shared__ uint32_t smu[];
    const int KS0 = 0, KS1 = 2560, VS0 = 5120, VS1 = 7680;

    const int tid  = threadIdx.x;
    const int lane = tid & 31;
    const int wm   = tid >> 5;
    const int g    = lane >> 2;
    const int t4   = lane & 3;
    const int qt   = (int)(gridDim.x - 1) - (int)blockIdx.x;  // long blocks first
    const int q0   = qt << 7;
    const int h    = blockIdx.y;
    const int b    = blockIdx.z;

    const size_t base  = ((size_t)(b * NUM_HEADS + h)) * T_SZ * 32;
    const size_t vbase = ((size_t)(b * NUM_HEADS + h)) * HEAD_DIM * (T_SZ / 2);
    const uint32_t smb = (uint32_t)__cvta_generic_to_shared(smu);
    const float NEG_INF = __int_as_float(0xff800000);

    // ---- stage Q (fp16x2 words, pre-scaled): rows 0-63 -> KS0, 64-127 -> KS1 ----
    {
        const uint32_t* Qp = Qg + base + (size_t)q0 * 32;
#pragma unroll
        for (int i = 0; i < 8; i++) {
            int c  = tid + (i << 7);          // 0..1023 chunks
            int r  = c >> 3;                  // row 0..127
            int c8 = (c & 7) << 2;            // word 0..28
            int off = (r < 64) ? (KS0 + r * GS + c8) : (KS1 + (r - 64) * GS + c8);
            cpa16(smb + (uint32_t)off * 4, Qp + (size_t)r * 32 + c8);
        }
    }
    CP_COMMIT(); CP_WAIT(0);
    __syncthreads();

    // ---- Q fragments -> registers (4 k16-steps) ----
    uint32_t qa[2][4][4];
#pragma unroll
    for (int mt = 0; mt < 2; mt++) {
        const uint32_t* Qs = smu + (mt ? KS1 : KS0);
        const int row = wm * 16 + g;
#pragma unroll
        for (int ks = 0; ks < 4; ks++) {
            int kk2 = ks * 8 + 2 * t4;
            uint2 u = *(const uint2*)&Qs[row * GS + kk2];
            uint2 v = *(const uint2*)&Qs[(row + 8) * GS + kk2];
            qa[mt][ks][0] = u.x; qa[mt][ks][1] = v.x;
            qa[mt][ks][2] = u.y; qa[mt][ks][3] = v.y;
        }
    }
    __syncthreads();

    auto stageKV = [&](int kt, int buf) {
        const uint32_t* Kp = Kg + base + (size_t)(kt << 6) * 32;
        const uint32_t* Vp = Vg + vbase + (kt << 5);
        const int ko = buf ? KS1 : KS0;
        const int vo = buf ? VS1 : VS0;
#pragma unroll
        for (int i = 0; i < 4; i++) {
            int c  = tid + (i << 7);          // 0..511 chunks
            int r  = c >> 3;                  // 0..63
            int c8 = (c & 7) << 2;
            cpa16(smb + (uint32_t)(ko + r * GS + c8) * 4, Kp + (size_t)r * 32 + c8);
            cpa16(smb + (uint32_t)(vo + r * GS + c8) * 4,
                  Vp + (size_t)r * (T_SZ / 2) + c8);
        }
    };

    stageKV(0, 0); CP_COMMIT();

    float4 o[2][8];
#pragma unroll
    for (int mt = 0; mt < 2; mt++)
#pragma unroll
        for (int dt = 0; dt < 8; dt++) o[mt][dt] = make_float4(0.f, 0.f, 0.f, 0.f);
    float mrow[2][2] = {{NEG_INF, NEG_INF}, {NEG_INF, NEG_INF}};
    float lrow[2][2] = {{0.f, 0.f}, {0.f, 0.f}};

    const int nkt = 2 * qt + 2;
    for (int kt = 0; kt < nkt; kt++) {
        if (kt + 1 < nkt) { stageKV(kt + 1, (kt + 1) & 1); CP_COMMIT(); CP_WAIT(1); }
        else              { CP_WAIT(0); }
        __syncthreads();

        const uint32_t* Kt = smu + ((kt & 1) ? KS1 : KS0);
        const uint32_t* Vt = smu + ((kt & 1) ? VS1 : VS0);
        const int k0 = kt << 6;
        const bool act0 = (kt <= 2 * qt);   // mt0 fully masked on last tile

        // ---- S = Q K^T (fp16 k16; K fragment = one LDS.64, hoisted over mt) ----
        float4 s[2][8];
#pragma unroll
        for (int mt = 0; mt < 2; mt++)
#pragma unroll
            for (int nt = 0; nt < 8; nt++) s[mt][nt] = make_float4(0.f, 0.f, 0.f, 0.f);
#pragma unroll
        for (int nt = 0; nt < 8; nt++) {
            const int rowb = (nt * 8 + g) * GS;
#pragma unroll
            for (int ks = 0; ks < 4; ks++) {
                uint2 bp = *(const uint2*)&Kt[rowb + ks * 8 + 2 * t4];
                if (act0) mma16h(s[0][nt], qa[0][ks], bp.x, bp.y, s[0][nt]);
                mma16h(s[1][nt], qa[1][ks], bp.x, bp.y, s[1][nt]);
            }
        }

        // ---- causal mask ----
        if (kt >= 2 * qt) {
#pragma unroll
            for (int mt = 0; mt < 2; mt++) {
                if (mt == 0 && !act0) continue;
                int rowA = q0 + mt * 64 + wm * 16 + g;
#pragma unroll
                for (int nt = 0; nt < 8; nt++) {
                    int c0 = k0 + nt * 8 + 2 * t4;
                    if (c0     > rowA)     s[mt][nt].x = NEG_INF;
                    if (c0 + 1 > rowA)     s[mt][nt].y = NEG_INF;
                    if (c0     > rowA + 8) s[mt][nt].z = NEG_INF;
                    if (c0 + 1 > rowA + 8) s[mt][nt].w = NEG_INF;
                }
            }
        }

        // ---- online softmax (base-2) + pack P to fp16 A-fragments ----
        uint32_t pa[2][4][4];
#pragma unroll
        for (int mt = 0; mt < 2; mt++) {
            if (mt == 0 && !act0) continue;
            float mx0 = NEG_INF, mx1 = NEG_INF;
#pragma unroll
            for (int nt = 0; nt < 8; nt++) {
                mx0 = fmaxf(mx0, fmaxf(s[mt][nt].x, s[mt][nt].y));
                mx1 = fmaxf(mx1, fmaxf(s[mt][nt].z, s[mt][nt].w));
            }
            mx0 = fmaxf(mx0, __shfl_xor_sync(0xffffffffu, mx0, 1));
            mx0 = fmaxf(mx0, __shfl_xor_sync(0xffffffffu, mx0, 2));
            mx1 = fmaxf(mx1, __shfl_xor_sync(0xffffffffu, mx1, 1));
            mx1 = fmaxf(mx1, __shfl_xor_sync(0xffffffffu, mx1, 2));

            float mn0 = fmaxf(mrow[mt][0], mx0), mn1 = fmaxf(mrow[mt][1], mx1);
            float fac0 = ex2(mrow[mt][0] - mn0), fac1 = ex2(mrow[mt][1] - mn1);
            float sum0 = 0.f, sum1 = 0.f;
#pragma unroll
            for (int nt = 0; nt < 8; nt++) {
                s[mt][nt].x = ex2(s[mt][nt].x - mn0);
                s[mt][nt].y = ex2(s[mt][nt].y - mn0);
                s[mt][nt].z = ex2(s[mt][nt].z - mn1);
                s[mt][nt].w = ex2(s[mt][nt].w - mn1);
                sum0 += s[mt][nt].x + s[mt][nt].y;
                sum1 += s[mt][nt].z + s[mt][nt].w;
            }
            sum0 += __shfl_xor_sync(0xffffffffu, sum0, 1);
            sum0 += __shfl_xor_sync(0xffffffffu, sum0, 2);
            sum1 += __shfl_xor_sync(0xffffffffu, sum1, 1);
            sum1 += __shfl_xor_sync(0xffffffffu, sum1, 2);
            lrow[mt][0] = lrow[mt][0] * fac0 + sum0;
            lrow[mt][1] = lrow[mt][1] * fac1 + sum1;
            mrow[mt][0] = mn0; mrow[mt][1] = mn1;
#pragma unroll
            for (int dt = 0; dt < 8; dt++) {
                o[mt][dt].x *= fac0; o[mt][dt].y *= fac0;
                o[mt][dt].z *= fac1; o[mt][dt].w *= fac1;
            }
#pragma unroll
            for (int kp = 0; kp < 4; kp++) {
                pa[mt][kp][0] = f16x2pack(s[mt][2 * kp].y,     s[mt][2 * kp].x);
                pa[mt][kp][1] = f16x2pack(s[mt][2 * kp].w,     s[mt][2 * kp].z);
                pa[mt][kp][2] = f16x2pack(s[mt][2 * kp + 1].y, s[mt][2 * kp + 1].x);
                pa[mt][kp][3] = f16x2pack(s[mt][2 * kp + 1].w, s[mt][2 * kp + 1].z);
            }
        }

        // ---- O += P V  (fp16 k16; V fragment = one LDS.64) ----
#pragma unroll
        for (int kp = 0; kp < 4; kp++) {
#pragma unroll
            for (int dt = 0; dt < 8; dt++) {
                uint2 vv = *(const uint2*)&Vt[(dt * 8 + g) * GS + kp * 8 + 2 * t4];
                if (act0) mma16h(o[0][dt], pa[0][kp], vv.x, vv.y, o[0][dt]);
                mma16h(o[1][dt], pa[1][kp], vv.x, vv.y, o[1][dt]);
            }
        }
        __syncthreads();   // all reads of this stage's K/V done before overwrite
    }

    // ---- epilogue: normalize, store fp16x2 word-permuted (feeds O-gemm) ----
#pragma unroll
    for (int mt = 0; mt < 2; mt++) {
        float inv0 = 1.0f / lrow[mt][0], inv1 = 1.0f / lrow[mt][1];
        int r1 = q0 + mt * 64 + wm * 16 + g;
        int r2 = r1 + 8;
        size_t ro1 = ((size_t)(b * T_SZ) + r1) * DW;
        size_t ro2 = ((size_t)(b * T_SZ) + r2) * DW;
#pragma unroll
        for (int dt = 0; dt < 8; dt++) {
            int gw = h * 32 + dt * 4 + t4;       // global word index (c0/2)
            int pw = wperm(gw);
            Og[ro1 + pw] = f16x2pack(o[mt][dt].y * inv0, o[mt][dt].x * inv0);
            Og[ro2 + pw] = f16x2pack(o[mt][dt].w * inv1, o[mt][dt].z * inv1);
        }
    }
}

// ---------------------------------------------------------------------------
extern "C" void kernel_launch(void* const* d_in, const int* in_sizes, int n_in,
                              void* d_out, int out_size)
{
    const float* x_q  = (const float*)d_in[0];
    const float* x_kv = (const float*)d_in[1];
    const float* Wq   = (const float*)d_in[2];
    const float* Wk   = (const float*)d_in[3];
    const float* Wv   = (const float*)d_in[4];
    const float* Wo   = (const float*)d_in[5];
    float* out = (float*)d_out;

    uint32_t *pxq, *pxkv, *pwq, *pwk, *pwv, *pwo, *pq, *pk, *pv, *pattn;
    cudaGetSymbolAddress((void**)&pxq,  g_xq);
    cudaGetSymbolAddress((void**)&pxkv, g_xkv);
    cudaGetSymbolAddress((void**)&pwq,  g_wq);
    cudaGetSymbolAddress((void**)&pwk,  g_wk);
    cudaGetSymbolAddress((void**)&pwv,  g_wv);
    cudaGetSymbolAddress((void**)&pwo,  g_wo);
    cudaGetSymbolAddress((void**)&pq,   g_q);
    cudaGetSymbolAddress((void**)&pk,   g_k);
    cudaGetSymbolAddress((void**)&pv,   g_v);
    cudaGetSymbolAddress((void**)&pattn, g_attn);

    const int ATTN_SMEM = 10240 * 4;                // 40960 B
    const int GEMM_SMEM = 4 * 5120 * 4;             // 81920 B
    cudaFuncSetAttribute(attn_tc_kernel,
                         cudaFuncAttributeMaxDynamicSharedMemorySize, ATTN_SMEM);
    cudaFuncSetAttribute(gemm_qkv_kernel,
                         cudaFuncAttributeMaxDynamicSharedMemorySize, GEMM_SMEM);
    cudaFuncSetAttribute(gemm_o_kernel,
                         cudaFuncAttributeMaxDynamicSharedMemorySize, GEMM_SMEM);

    // ---- pre-convert + word-permute ALL inputs/weights in ONE launch ----
    CvtArgs ca;
    ca.src[0] = x_q;  ca.dst[0] = pxq;
    ca.src[1] = x_kv; ca.dst[1] = pxkv;
    ca.src[2] = Wq;   ca.dst[2] = pwq;
    ca.src[3] = Wk;   ca.dst[3] = pwk;
    ca.src[4] = Wv;   ca.dst[4] = pwv;
    ca.src[5] = Wo;   ca.dst[5] = pwo;
    cvtp_all_kernel<<<4096 + 4 * 256, 256>>>(ca);

    // ---- fused Q/K/V projections ----
    gemm_qkv_kernel<<<dim3(D_MODEL / 128, M_ROWS / 128, 3), 256, GEMM_SMEM>>>();

    // ---- attention ----
    attn_tc_kernel<<<dim3(T_SZ / 128, NUM_HEADS, B_SZ), 128, ATTN_SMEM>>>(pq, pk, pv, pattn);

    // ---- output projection ----
    gemm_o_kernel<<<dim3(D_MODEL / 128, M_ROWS / 128), 256, GEMM_SMEM>>>(out);
}